// round 16
// baseline (speedup 1.0000x reference)
#include <cuda_runtime.h>
#include <cuda_fp16.h>
#include <cstdint>

// ---------------------------------------------------------------------------
// FINAL: fp16 m16n8k16 mma.sync, fp32 accum. M_tile=128, 4 warps (2Mx2N of
// 64x64 warp tiles), 2 CTAs/SM. Double-buffered X/W via cp.async; A-frags
// register-double-buffered, B-frags grouped per k16. Weights pre-transposed/
// rounded/shuffled into exact SMEM byte images by a prep pass (3 tight
// launches to minimize prologue time).
//
// This runs at the measured sm_103 wall for legacy mma.sync: 5.0 cyc/instr/SM
// (invariant across tf32/fp16, f16/f32 accum, 4-16 warps, 2-4 CTAs/SM).
// 34.6M instructions -> ~617us kernel. Falsified alternatives: tcgen05
// (ptxas-blocked on compute_103), int8/fp8 (more instrs), f16-accum (same
// rate, worse error), hybrid FFMA CTAs (4 attempts, all net-negative).
// ---------------------------------------------------------------------------

struct Params {
    const float* x;
    const float* w1[5]; const float* b1[5];
    const float* w2[5]; const float* b2[5];
    const float* w3[5]; const float* b3[5];
    float* out;
};

__constant__ int c_gi[21]  = {0,1,1,1,2,2,3,3,3,3,3,3,3,3,3,3,4,4,4,4,4};
__constant__ int c_ki[21]  = {0,0,1,2,0,1,0,1,2,3,4,5,6,7,8,9,0,1,2,3,4};
__constant__ int c_n[21]   = {6,5,5,5,4,4,3,3,3,3,3,3,3,3,3,3,2,2,2,2,2};
__constant__ int c_out[21] = {0,5,9,13,1,17,2,3,6,7,10,11,14,15,18,19,4,8,12,16,20};
__constant__ int c_nb[21][6] = {
    {0,1,5,9,13,17},
    {0,5,6,1,9,0},  {0,9,10,5,13,0}, {0,13,14,9,17,0},
    {0,1,2,5,0,0},  {0,17,18,13,0,0},
    {1,2,3,0,0,0},  {2,3,4,0,0,0},
    {5,6,7,0,0,0},  {6,7,8,0,0,0},
    {9,10,11,0,0,0},{10,11,12,0,0,0},
    {13,14,15,0,0,0},{14,15,16,0,0,0},
    {17,18,19,0,0,0},{18,19,20,0,0,0},
    {3,4,0,0,0,0},  {7,8,0,0,0,0}, {11,12,0,0,0,0},
    {15,16,0,0,0,0},{19,20,0,0,0,0}
};
// per-node half-offset of W1 image (chunks of 8192 halves = one 64-k slab)
__constant__ int c_w1i_off[21] = {
    0,49152,90112,131072,172032,204800,
    237568,262144,286720,311296,335872,360448,385024,409600,434176,458752,
    483328,499712,516096,532480,548864
};

// Pre-shuffled fp16 weight images (exact SMEM byte layout)
__device__ __align__(16) __half g_w1i[565248];
__device__ __align__(16) __half g_w2i[344064];   // 21 * 2 * 8192
__device__ __align__(16) __half g_w3i[172032];   // 21 * 8192

// SMEM map (bytes). Tiles: 16 rows x 32B. HA 512B, XA 528B (pad), WB 256B.
#define SM_HA 0                      // 64 tiles * 512 = 32768
#define SM_XA 32768                  // 2 bufs * 32 tiles * 528 = 33792
#define XA_BUF 16896
#define SM_WB 66560                  // 2 bufs * 16384
#define WB_BUF 16384
#define SMEM_TOTAL 99328

__device__ __forceinline__ uint32_t pkh2(float lo, float hi) {
    uint32_t r;   // low half = lo
    asm("cvt.rn.f16x2.f32 %0, %1, %2;" : "=r"(r) : "f"(hi), "f"(lo));
    return r;
}

__device__ __forceinline__ void mma16(float c[4],
                                      uint32_t a0, uint32_t a1, uint32_t a2, uint32_t a3,
                                      uint32_t b0, uint32_t b1) {
    asm volatile(
        "mma.sync.aligned.m16n8k16.row.col.f32.f16.f16.f32 "
        "{%0,%1,%2,%3},{%4,%5,%6,%7},{%8,%9},{%0,%1,%2,%3};"
        : "+f"(c[0]), "+f"(c[1]), "+f"(c[2]), "+f"(c[3])
        : "r"(a0), "r"(a1), "r"(a2), "r"(a3), "r"(b0), "r"(b1));
}
__device__ __forceinline__ void domma(float c[4], uint2 Pg, uint2 Pg8, uint2 Pb) {
    mma16(c, Pg.x, Pg8.x, Pg.y, Pg8.y, Pb.x, Pb.y);
}

#define CP16(dst, src) \
    asm volatile("cp.async.ca.shared.global [%0], [%1], 16;" :: "r"(dst), "l"(src))
#define CP_COMMIT() asm volatile("cp.async.commit_group;" ::: "memory")
#define CP_WAIT0()  asm volatile("cp.async.wait_group 0;" ::: "memory")

__device__ __forceinline__ uint32_t smem_u32(const void* p) {
    uint32_t a;
    asm("{ .reg .u64 t; cvta.to.shared.u64 t, %1; cvt.u32.u64 %0, t; }"
        : "=r"(a) : "l"(p));
    return a;
}

// ------------------------------ prep kernels -------------------------------
// Image half-offset; B tile stride = 128 halves (8 rows x 32B). Verified R6+.
__device__ __forceinline__ int imgh(int n, int k, int K16, int NK16c) {
    int jw = (k & 15) >> 1, lo = k & 1;
    int rn = n & 7, NB = n >> 3, s = (rn >> 2) & 1;
    return (NB * NK16c + K16) * 128 + rn * 16 +
           ((((jw >> 1) & 1) ^ s) << 3) + ((jw & 1) << 2) + ((jw >> 2) << 1) + lo;
}

__global__ void prep_w1(Params p) {
    const int node = blockIdx.y;
    const int gi = c_gi[node], ki = c_ki[node], nnb = c_n[node];
    const int i = blockIdx.x * 256 + threadIdx.x;
    const int K1 = nnb * 64;
    if (i >= 128 * K1) return;
    const int k = i >> 7, n = i & 127;
    float v = p.w1[gi][((size_t)ki * K1 + k) * 128 + n];
    g_w1i[c_w1i_off[node] + (k >> 6) * 8192 + imgh(n, k, (k >> 4) & 3, 4)] =
        __float2half_rn(v);
}

__global__ void prep_w2(Params p) {
    const int node = blockIdx.y;
    const int gi = c_gi[node], ki = c_ki[node];
    const int i = blockIdx.x * 256 + threadIdx.x;   // i < 16384 by grid sizing
    const int k = i >> 7, n = i & 127;
    float v = p.w2[gi][(size_t)ki * 16384 + (size_t)k * 128 + n];
    g_w2i[node * 16384 + (k >> 6) * 8192 + imgh(n, k, (k >> 4) & 3, 4)] =
        __float2half_rn(v);
}

__global__ void prep_w3(Params p) {
    const int node = blockIdx.y;
    const int gi = c_gi[node], ki = c_ki[node];
    const int i = blockIdx.x * 256 + threadIdx.x;   // i < 8192 by grid sizing
    const int k = i >> 6, n = i & 63;
    float v = p.w3[gi][(size_t)ki * 8192 + (size_t)k * 64 + n];
    g_w3i[node * 8192 + imgh(n, k, k >> 4, 8)] = __float2half_rn(v);
}

// ------------------------------ main kernel --------------------------------

__global__ __launch_bounds__(128, 2)
void mp16_kernel(Params p) {
    extern __shared__ char smem[];
    const int tid = threadIdx.x;
    const int w = tid >> 5, lane = tid & 31;
    const int g = lane >> 2, t4 = lane & 3;
    const int node = blockIdx.x;
    const int m0 = blockIdx.y * 128;
    const int gi = c_gi[node], ki = c_ki[node], nnb = c_n[node];
    const int wm = w & 1, wn = w >> 1;          // 2M x 2N grid of 64x64 tiles
    const int sg = (g >> 2) & 1;
    const int awl  = (((t4 >> 1) ^ sg) << 4) + ((t4 & 1) << 3);
    const int aoff = g * 32 + awl;

    const uint32_t sbWB = smem_u32(smem + SM_WB);

    float acc[4][8][4];
    #pragma unroll
    for (int mi = 0; mi < 4; ++mi)
        #pragma unroll
        for (int ni = 0; ni < 8; ++ni)
            #pragma unroll
            for (int r = 0; r < 4; ++r) acc[mi][ni][r] = 0.f;

    #define ISSUE_W(ws, buf) do {                                         \
        uint32_t _d = sbWB + (buf) * WB_BUF;                              \
        const __half* _s = (ws);                                          \
        _Pragma("unroll")                                                 \
        for (int _i = 0; _i < 8; ++_i) {                                  \
            int _idx = tid + _i * 128;                                    \
            CP16(_d + _idx * 16, _s + _idx * 8);                          \
        }                                                                 \
        CP_COMMIT();                                                      \
    } while (0)

    #define STORE_X(joint, buf) do {                                      \
        const float* _xb = p.x + (size_t)m0 * 1344 + (joint) * 64;        \
        char* _xa = smem + SM_XA + (buf) * XA_BUF;                        \
        _Pragma("unroll")                                                 \
        for (int _i = 0; _i < 4; ++_i) {                                  \
            int _v = tid + _i * 128;                                      \
            int _m = _v >> 2, _kt = _v & 3;                               \
            const float* _s = _xb + (size_t)_m * 1344 + _kt * 16;         \
            float4 A0 = *(const float4*)_s;                               \
            float4 A1 = *(const float4*)(_s + 4);                         \
            float4 A2 = *(const float4*)(_s + 8);                         \
            float4 A3 = *(const float4*)(_s + 12);                        \
            uint4 q0 = make_uint4(pkh2(A0.x, A0.y), pkh2(A2.x, A2.y),     \
                                  pkh2(A0.z, A0.w), pkh2(A2.z, A2.w));    \
            uint4 q1 = make_uint4(pkh2(A1.x, A1.y), pkh2(A3.x, A3.y),     \
                                  pkh2(A1.z, A1.w), pkh2(A3.z, A3.w));    \
            int _r = _m & 15, _R = _m >> 4;                               \
            char* _dst = _xa + (_R * 4 + _kt) * 528 + _r * 32;            \
            int _sw = (_r & 4) << 2;                                      \
            *(uint4*)(_dst + _sw) = q0;                                   \
            *(uint4*)(_dst + (16 ^ _sw)) = q1;                            \
        }                                                                 \
    } while (0)

    const __half* w1i = g_w1i + c_w1i_off[node];
    const __half* w2i = g_w2i + node * 16384;
    const __half* w3i = g_w3i + node * 8192;

    // prologue: chunk 0 into buffers 0
    ISSUE_W(w1i, 0);
    STORE_X(c_nb[node][0], 0);
    CP_WAIT0();
    __syncthreads();

    // ============================ Layer 1 ================================
    #pragma unroll 1
    for (int c = 0; c < nnb; ++c) {
        const int cu = c & 1, nx = cu ^ 1;
        if (c + 1 < nnb) {
            ISSUE_W(w1i + (c + 1) * 8192, nx);
            STORE_X(c_nb[node][c + 1], nx);
        } else {
            ISSUE_W(w2i, nx);
        }
        const char* xa = smem + SM_XA + cu * XA_BUF;
        const char* wb = smem + SM_WB + cu * WB_BUF;

        // pipelined fragment loads: A double-buffered, B grouped per step
        uint2 a[2][4][2];
        #pragma unroll
        for (int mi = 0; mi < 4; ++mi) {
            const char* ap = xa + ((wm * 4 + mi) * 4 + 0) * 528 + aoff;
            a[0][mi][0] = *(const uint2*)ap;
            a[0][mi][1] = *(const uint2*)(ap + 256);
        }
        #pragma unroll
        for (int k16 = 0; k16 < 4; ++k16) {
            const int cb = k16 & 1, nb = cb ^ 1;
            uint2 b[8];
            #pragma unroll
            for (int ni = 0; ni < 8; ++ni)
                b[ni] = *(const uint2*)(wb + ((wn * 8 + ni) * 4 + k16) * 256 + aoff);
            if (k16 < 3) {
                #pragma unroll
                for (int mi = 0; mi < 4; ++mi) {
                    const char* ap = xa + ((wm * 4 + mi) * 4 + k16 + 1) * 528 + aoff;
                    a[nb][mi][0] = *(const uint2*)ap;
                    a[nb][mi][1] = *(const uint2*)(ap + 256);
                }
            }
            #pragma unroll
            for (int ni = 0; ni < 8; ++ni)
                #pragma unroll
                for (int mi = 0; mi < 4; ++mi)
                    domma(acc[mi][ni], a[cb][mi][0], a[cb][mi][1], b[ni]);
        }
        CP_WAIT0();
        __syncthreads();
    }
    const int b0 = nnb & 1;   // W2 chunk0 buffer

    // epilogue 1: prefetch W2 chunk1, bias + relu -> HA
    ISSUE_W(w2i + 8192, b0 ^ 1);
    {
        const float* bp = p.b1[gi] + ki * 128;
        #pragma unroll
        for (int ni = 0; ni < 8; ++ni) {
            int col0 = wn * 64 + ni * 8 + 2 * t4;
            float2 bb = *(const float2*)(bp + col0);
            int kt = wn * 4 + (ni >> 1);
            int off = awl + ((ni & 1) << 2);
            #pragma unroll
            for (int mi = 0; mi < 4; ++mi) {
                char* base = smem + SM_HA + ((wm * 4 + mi) * 8 + kt) * 512 + g * 32 + off;
                *(uint32_t*)base = pkh2(fmaxf(acc[mi][ni][0] + bb.x, 0.f),
                                        fmaxf(acc[mi][ni][1] + bb.y, 0.f));
                *(uint32_t*)(base + 256) = pkh2(fmaxf(acc[mi][ni][2] + bb.x, 0.f),
                                                fmaxf(acc[mi][ni][3] + bb.y, 0.f));
                acc[mi][ni][0] = acc[mi][ni][1] = acc[mi][ni][2] = acc[mi][ni][3] = 0.f;
            }
        }
    }
    __syncthreads();

    // ============================ Layer 2 ================================
    #pragma unroll 1
    for (int c = 0; c < 2; ++c) {
        if (c == 1) ISSUE_W(w3i, b0);   // prefetch W3 into chunk0's buffer
        const char* wb = smem + SM_WB + ((c == 0) ? b0 : (b0 ^ 1)) * WB_BUF;

        uint2 a[2][4][2];
        #pragma unroll
        for (int mi = 0; mi < 4; ++mi) {
            const char* ap = smem + SM_HA + ((wm * 4 + mi) * 8 + c * 4) * 512 + aoff;
            a[0][mi][0] = *(const uint2*)ap;
            a[0][mi][1] = *(const uint2*)(ap + 256);
        }
        #pragma unroll
        for (int k16 = 0; k16 < 4; ++k16) {
            const int cb = k16 & 1, nb = cb ^ 1;
            uint2 b[8];
            #pragma unroll
            for (int ni = 0; ni < 8; ++ni)
                b[ni] = *(const uint2*)(wb + ((wn * 8 + ni) * 4 + k16) * 256 + aoff);
            if (k16 < 3) {
                #pragma unroll
                for (int mi = 0; mi < 4; ++mi) {
                    const char* ap = smem + SM_HA +
                        ((wm * 4 + mi) * 8 + c * 4 + k16 + 1) * 512 + aoff;
                    a[nb][mi][0] = *(const uint2*)ap;
                    a[nb][mi][1] = *(const uint2*)(ap + 256);
                }
            }
            #pragma unroll
            for (int ni = 0; ni < 8; ++ni)
                #pragma unroll
                for (int mi = 0; mi < 4; ++mi)
                    domma(acc[mi][ni], a[cb][mi][0], a[cb][mi][1], b[ni]);
        }
        CP_WAIT0();
        __syncthreads();
    }

    // epilogue 2: bias + relu -> HA (in place; layer-2 reads done at barrier)
    {
        const float* bp = p.b2[gi] + ki * 128;
        #pragma unroll
        for (int ni = 0; ni < 8; ++ni) {
            int col0 = wn * 64 + ni * 8 + 2 * t4;
            float2 bb = *(const float2*)(bp + col0);
            int kt = wn * 4 + (ni >> 1);
            int off = awl + ((ni & 1) << 2);
            #pragma unroll
            for (int mi = 0; mi < 4; ++mi) {
                char* base = smem + SM_HA + ((wm * 4 + mi) * 8 + kt) * 512 + g * 32 + off;
                *(uint32_t*)base = pkh2(fmaxf(acc[mi][ni][0] + bb.x, 0.f),
                                        fmaxf(acc[mi][ni][1] + bb.y, 0.f));
                *(uint32_t*)(base + 256) = pkh2(fmaxf(acc[mi][ni][2] + bb.x, 0.f),
                                                fmaxf(acc[mi][ni][3] + bb.y, 0.f));
                acc[mi][ni][0] = acc[mi][ni][1] = acc[mi][ni][2] = acc[mi][ni][3] = 0.f;
            }
        }
    }
    __syncthreads();

    // ============================ Layer 3 ================================
    {
        const char* wb = smem + SM_WB + b0 * WB_BUF;   // W3 (waited at L2 end)
        uint2 a[2][4][2];
        #pragma unroll
        for (int mi = 0; mi < 4; ++mi) {
            const char* ap = smem + SM_HA + ((wm * 4 + mi) * 8 + 0) * 512 + aoff;
            a[0][mi][0] = *(const uint2*)ap;
            a[0][mi][1] = *(const uint2*)(ap + 256);
        }
        #pragma unroll
        for (int k16 = 0; k16 < 8; ++k16) {
            const int cb = k16 & 1, nb = cb ^ 1;
            uint2 b[4];
            #pragma unroll
            for (int ni = 0; ni < 4; ++ni)
                b[ni] = *(const uint2*)(wb + ((wn * 4 + ni) * 8 + k16) * 256 + aoff);
            if (k16 < 7) {
                #pragma unroll
                for (int mi = 0; mi < 4; ++mi) {
                    const char* ap = smem + SM_HA +
                        ((wm * 4 + mi) * 8 + k16 + 1) * 512 + aoff;
                    a[nb][mi][0] = *(const uint2*)ap;
                    a[nb][mi][1] = *(const uint2*)(ap + 256);
                }
            }
            #pragma unroll
            for (int ni = 0; ni < 4; ++ni)
                #pragma unroll
                for (int mi = 0; mi < 4; ++mi)
                    domma(acc[mi][ni], a[cb][mi][0], a[cb][mi][1], b[ni]);
        }
    }

    // epilogue 3: bias, f32 STG.64 direct
    {
        const float* bp = p.b3[gi] + ki * 64;
        const int oj = c_out[node] * 64;
        #pragma unroll
        for (int ni = 0; ni < 4; ++ni) {
            int col0 = wn * 32 + ni * 8 + 2 * t4;
            float2 bb = *(const float2*)(bp + col0);
            #pragma unroll
            for (int mi = 0; mi < 4; ++mi) {
                size_t ro = (size_t)(m0 + wm * 64 + mi * 16 + g) * 1344 + oj + col0;
                *(float2*)(p.out + ro) =
                    make_float2(acc[mi][ni][0] + bb.x, acc[mi][ni][1] + bb.y);
                *(float2*)(p.out + ro + (size_t)8 * 1344) =
                    make_float2(acc[mi][ni][2] + bb.x, acc[mi][ni][3] + bb.y);
            }
        }
    }
    #undef ISSUE_W
    #undef STORE_X
}

// ------------------------------ launch -------------------------------------

extern "C" void kernel_launch(void* const* d_in, const int* in_sizes, int n_in,
                              void* d_out, int out_size) {
    (void)n_in; (void)out_size;
    Params p;
    p.x = (const float*)d_in[0];
    int idx = 1;
    for (int gi = 0; gi < 5; ++gi) {
        p.w1[gi] = (const float*)d_in[idx++];
        p.b1[gi] = (const float*)d_in[idx++];
        p.w2[gi] = (const float*)d_in[idx++];
        p.b2[gi] = (const float*)d_in[idx++];
        p.w3[gi] = (const float*)d_in[idx++];
        p.b3[gi] = (const float*)d_in[idx++];
    }
    p.out = (float*)d_out;

    const int B = in_sizes[0] / (21 * 64);

    // Prep: three tight launches (w1 max 49152 elems -> 192 x-blocks;
    // w2 16384 -> 64; w3 8192 -> 32). Ballast blocks minimized.
    prep_w1<<<dim3(192, 21), 256>>>(p);
    prep_w2<<<dim3(64, 21), 256>>>(p);
    prep_w3<<<dim3(32, 21), 256>>>(p);

    cudaFuncSetAttribute(mp16_kernel, cudaFuncAttributeMaxDynamicSharedMemorySize,
                         SMEM_TOTAL);
    dim3 grid(21, B / 128);
    mp16_kernel<<<grid, 128, SMEM_TOTAL>>>(p);
}

// round 17
// speedup vs baseline: 1.0040x; 1.0040x over previous
#include <cuda_runtime.h>
#include <cuda_fp16.h>
#include <cstdint>

// ---------------------------------------------------------------------------
// FINAL: fp16 m16n8k16 mma.sync, fp32 accum. M_tile=128, 4 warps (2Mx2N of
// 64x64 warp tiles), 2 CTAs/SM. Double-buffered X/W via cp.async; A-frags
// register-double-buffered, B-frags grouped per k16. Weights pre-transposed/
// rounded/shuffled into exact SMEM byte images by ONE ballast-free prep
// launch (flat index over all three images, 4224 blocks).
//
// Main kernel runs at the measured sm_103 wall for legacy mma.sync:
// 5.0 cyc/instr/SM (invariant across tf32/fp16, f16/f32 accum, 4-16 warps,
// 2-4 CTAs/SM). 34.6M instructions -> ~617us. Falsified alternatives:
// tcgen05 (ptxas-blocked on compute_103), int8/fp8 (more instrs), f16-accum
// (same rate, worse error), hybrid FFMA CTAs (4 attempts, all net-negative).
// ---------------------------------------------------------------------------

struct Params {
    const float* x;
    const float* w1[5]; const float* b1[5];
    const float* w2[5]; const float* b2[5];
    const float* w3[5]; const float* b3[5];
    float* out;
};

__constant__ int c_gi[21]  = {0,1,1,1,2,2,3,3,3,3,3,3,3,3,3,3,4,4,4,4,4};
__constant__ int c_ki[21]  = {0,0,1,2,0,1,0,1,2,3,4,5,6,7,8,9,0,1,2,3,4};
__constant__ int c_n[21]   = {6,5,5,5,4,4,3,3,3,3,3,3,3,3,3,3,2,2,2,2,2};
__constant__ int c_out[21] = {0,5,9,13,1,17,2,3,6,7,10,11,14,15,18,19,4,8,12,16,20};
__constant__ int c_nb[21][6] = {
    {0,1,5,9,13,17},
    {0,5,6,1,9,0},  {0,9,10,5,13,0}, {0,13,14,9,17,0},
    {0,1,2,5,0,0},  {0,17,18,13,0,0},
    {1,2,3,0,0,0},  {2,3,4,0,0,0},
    {5,6,7,0,0,0},  {6,7,8,0,0,0},
    {9,10,11,0,0,0},{10,11,12,0,0,0},
    {13,14,15,0,0,0},{14,15,16,0,0,0},
    {17,18,19,0,0,0},{18,19,20,0,0,0},
    {3,4,0,0,0,0},  {7,8,0,0,0,0}, {11,12,0,0,0,0},
    {15,16,0,0,0,0},{19,20,0,0,0,0}
};
// per-node half-offset of W1 image == prefix sum of 128*K1 (exact)
__constant__ int c_w1i_off[22] = {
    0,49152,90112,131072,172032,204800,
    237568,262144,286720,311296,335872,360448,385024,409600,434176,458752,
    483328,499712,516096,532480,548864,565248
};

// Pre-shuffled fp16 weight images (exact SMEM byte layout)
__device__ __align__(16) __half g_w1i[565248];
__device__ __align__(16) __half g_w2i[344064];   // 21 * 2 * 8192
__device__ __align__(16) __half g_w3i[172032];   // 21 * 8192

// SMEM map (bytes). Tiles: 16 rows x 32B. HA 512B, XA 528B (pad), WB 256B.
#define SM_HA 0                      // 64 tiles * 512 = 32768
#define SM_XA 32768                  // 2 bufs * 32 tiles * 528 = 33792
#define XA_BUF 16896
#define SM_WB 66560                  // 2 bufs * 16384
#define WB_BUF 16384
#define SMEM_TOTAL 99328

__device__ __forceinline__ uint32_t pkh2(float lo, float hi) {
    uint32_t r;   // low half = lo
    asm("cvt.rn.f16x2.f32 %0, %1, %2;" : "=r"(r) : "f"(hi), "f"(lo));
    return r;
}

__device__ __forceinline__ void mma16(float c[4],
                                      uint32_t a0, uint32_t a1, uint32_t a2, uint32_t a3,
                                      uint32_t b0, uint32_t b1) {
    asm volatile(
        "mma.sync.aligned.m16n8k16.row.col.f32.f16.f16.f32 "
        "{%0,%1,%2,%3},{%4,%5,%6,%7},{%8,%9},{%0,%1,%2,%3};"
        : "+f"(c[0]), "+f"(c[1]), "+f"(c[2]), "+f"(c[3])
        : "r"(a0), "r"(a1), "r"(a2), "r"(a3), "r"(b0), "r"(b1));
}
__device__ __forceinline__ void domma(float c[4], uint2 Pg, uint2 Pg8, uint2 Pb) {
    mma16(c, Pg.x, Pg8.x, Pg.y, Pg8.y, Pb.x, Pb.y);
}

#define CP16(dst, src) \
    asm volatile("cp.async.ca.shared.global [%0], [%1], 16;" :: "r"(dst), "l"(src))
#define CP_COMMIT() asm volatile("cp.async.commit_group;" ::: "memory")
#define CP_WAIT0()  asm volatile("cp.async.wait_group 0;" ::: "memory")

__device__ __forceinline__ uint32_t smem_u32(const void* p) {
    uint32_t a;
    asm("{ .reg .u64 t; cvta.to.shared.u64 t, %1; cvt.u32.u64 %0, t; }"
        : "=r"(a) : "l"(p));
    return a;
}

// ------------------------------ prep kernel --------------------------------
// Image half-offset; B tile stride = 128 halves (8 rows x 32B). Verified R6+.
__device__ __forceinline__ int imgh(int n, int k, int K16, int NK16c) {
    int jw = (k & 15) >> 1, lo = k & 1;
    int rn = n & 7, NB = n >> 3, s = (rn >> 2) & 1;
    return (NB * NK16c + K16) * 128 + rn * 16 +
           ((((jw >> 1) & 1) ^ s) << 3) + ((jw & 1) << 2) + ((jw >> 2) << 1) + lo;
}

#define W1_TOTAL 565248
#define W2_TOTAL 344064
// flat elements = 565248 + 344064 + 172032 = 1081344 -> 4224 blocks of 256
__global__ void prep_all(Params p) {
    const int i = blockIdx.x * 256 + threadIdx.x;
    if (i < W1_TOTAL) {
        // node lookup via prefix-sum scan (21 compares; memory-bound anyway)
        int node = 0;
        #pragma unroll
        for (int t = 1; t < 21; ++t)
            if (i >= c_w1i_off[t]) node = t;
        const int gi = c_gi[node], ki = c_ki[node], nnb = c_n[node];
        const int K1 = nnb * 64;
        const int local = i - c_w1i_off[node];
        const int k = local >> 7, n = local & 127;
        float v = p.w1[gi][((size_t)ki * K1 + k) * 128 + n];
        g_w1i[c_w1i_off[node] + (k >> 6) * 8192 + imgh(n, k, (k >> 4) & 3, 4)] =
            __float2half_rn(v);
    } else if (i < W1_TOTAL + W2_TOTAL) {
        const int j = i - W1_TOTAL;
        const int node = j >> 14, jj = j & 16383;
        const int gi = c_gi[node], ki = c_ki[node];
        const int k = jj >> 7, n = jj & 127;
        float v = p.w2[gi][(size_t)ki * 16384 + (size_t)k * 128 + n];
        g_w2i[node * 16384 + (k >> 6) * 8192 + imgh(n, k, (k >> 4) & 3, 4)] =
            __float2half_rn(v);
    } else {
        const int j = i - (W1_TOTAL + W2_TOTAL);
        const int node = j >> 13, jj = j & 8191;
        const int gi = c_gi[node], ki = c_ki[node];
        const int k = jj >> 6, n = jj & 63;
        float v = p.w3[gi][(size_t)ki * 8192 + (size_t)k * 64 + n];
        g_w3i[node * 8192 + imgh(n, k, k >> 4, 8)] = __float2half_rn(v);
    }
}

// ------------------------------ main kernel --------------------------------

__global__ __launch_bounds__(128, 2)
void mp17_kernel(Params p) {
    extern __shared__ char smem[];
    const int tid = threadIdx.x;
    const int w = tid >> 5, lane = tid & 31;
    const int g = lane >> 2, t4 = lane & 3;
    const int node = blockIdx.x;
    const int m0 = blockIdx.y * 128;
    const int gi = c_gi[node], ki = c_ki[node], nnb = c_n[node];
    const int wm = w & 1, wn = w >> 1;          // 2M x 2N grid of 64x64 tiles
    const int sg = (g >> 2) & 1;
    const int awl  = (((t4 >> 1) ^ sg) << 4) + ((t4 & 1) << 3);
    const int aoff = g * 32 + awl;

    const uint32_t sbWB = smem_u32(smem + SM_WB);

    float acc[4][8][4];
    #pragma unroll
    for (int mi = 0; mi < 4; ++mi)
        #pragma unroll
        for (int ni = 0; ni < 8; ++ni)
            #pragma unroll
            for (int r = 0; r < 4; ++r) acc[mi][ni][r] = 0.f;

    #define ISSUE_W(ws, buf) do {                                         \
        uint32_t _d = sbWB + (buf) * WB_BUF;                              \
        const __half* _s = (ws);                                          \
        _Pragma("unroll")                                                 \
        for (int _i = 0; _i < 8; ++_i) {                                  \
            int _idx = tid + _i * 128;                                    \
            CP16(_d + _idx * 16, _s + _idx * 8);                          \
        }                                                                 \
        CP_COMMIT();                                                      \
    } while (0)

    #define STORE_X(joint, buf) do {                                      \
        const float* _xb = p.x + (size_t)m0 * 1344 + (joint) * 64;        \
        char* _xa = smem + SM_XA + (buf) * XA_BUF;                        \
        _Pragma("unroll")                                                 \
        for (int _i = 0; _i < 4; ++_i) {                                  \
            int _v = tid + _i * 128;                                      \
            int _m = _v >> 2, _kt = _v & 3;                               \
            const float* _s = _xb + (size_t)_m * 1344 + _kt * 16;         \
            float4 A0 = *(const float4*)_s;                               \
            float4 A1 = *(const float4*)(_s + 4);                         \
            float4 A2 = *(const float4*)(_s + 8);                         \
            float4 A3 = *(const float4*)(_s + 12);                        \
            uint4 q0 = make_uint4(pkh2(A0.x, A0.y), pkh2(A2.x, A2.y),     \
                                  pkh2(A0.z, A0.w), pkh2(A2.z, A2.w));    \
            uint4 q1 = make_uint4(pkh2(A1.x, A1.y), pkh2(A3.x, A3.y),     \
                                  pkh2(A1.z, A1.w), pkh2(A3.z, A3.w));    \
            int _r = _m & 15, _R = _m >> 4;                               \
            char* _dst = _xa + (_R * 4 + _kt) * 528 + _r * 32;            \
            int _sw = (_r & 4) << 2;                                      \
            *(uint4*)(_dst + _sw) = q0;                                   \
            *(uint4*)(_dst + (16 ^ _sw)) = q1;                            \
        }                                                                 \
    } while (0)

    const __half* w1i = g_w1i + c_w1i_off[node];
    const __half* w2i = g_w2i + node * 16384;
    const __half* w3i = g_w3i + node * 8192;

    // prologue: chunk 0 into buffers 0
    ISSUE_W(w1i, 0);
    STORE_X(c_nb[node][0], 0);
    CP_WAIT0();
    __syncthreads();

    // ============================ Layer 1 ================================
    #pragma unroll 1
    for (int c = 0; c < nnb; ++c) {
        const int cu = c & 1, nx = cu ^ 1;
        if (c + 1 < nnb) {
            ISSUE_W(w1i + (c + 1) * 8192, nx);
            STORE_X(c_nb[node][c + 1], nx);
        } else {
            ISSUE_W(w2i, nx);
        }
        const char* xa = smem + SM_XA + cu * XA_BUF;
        const char* wb = smem + SM_WB + cu * WB_BUF;

        // pipelined fragment loads: A double-buffered, B grouped per step
        uint2 a[2][4][2];
        #pragma unroll
        for (int mi = 0; mi < 4; ++mi) {
            const char* ap = xa + ((wm * 4 + mi) * 4 + 0) * 528 + aoff;
            a[0][mi][0] = *(const uint2*)ap;
            a[0][mi][1] = *(const uint2*)(ap + 256);
        }
        #pragma unroll
        for (int k16 = 0; k16 < 4; ++k16) {
            const int cb = k16 & 1, nb = cb ^ 1;
            uint2 b[8];
            #pragma unroll
            for (int ni = 0; ni < 8; ++ni)
                b[ni] = *(const uint2*)(wb + ((wn * 8 + ni) * 4 + k16) * 256 + aoff);
            if (k16 < 3) {
                #pragma unroll
                for (int mi = 0; mi < 4; ++mi) {
                    const char* ap = xa + ((wm * 4 + mi) * 4 + k16 + 1) * 528 + aoff;
                    a[nb][mi][0] = *(const uint2*)ap;
                    a[nb][mi][1] = *(const uint2*)(ap + 256);
                }
            }
            #pragma unroll
            for (int ni = 0; ni < 8; ++ni)
                #pragma unroll
                for (int mi = 0; mi < 4; ++mi)
                    domma(acc[mi][ni], a[cb][mi][0], a[cb][mi][1], b[ni]);
        }
        CP_WAIT0();
        __syncthreads();
    }
    const int b0 = nnb & 1;   // W2 chunk0 buffer

    // epilogue 1: prefetch W2 chunk1, bias + relu -> HA
    ISSUE_W(w2i + 8192, b0 ^ 1);
    {
        const float* bp = p.b1[gi] + ki * 128;
        #pragma unroll
        for (int ni = 0; ni < 8; ++ni) {
            int col0 = wn * 64 + ni * 8 + 2 * t4;
            float2 bb = *(const float2*)(bp + col0);
            int kt = wn * 4 + (ni >> 1);
            int off = awl + ((ni & 1) << 2);
            #pragma unroll
            for (int mi = 0; mi < 4; ++mi) {
                char* base = smem + SM_HA + ((wm * 4 + mi) * 8 + kt) * 512 + g * 32 + off;
                *(uint32_t*)base = pkh2(fmaxf(acc[mi][ni][0] + bb.x, 0.f),
                                        fmaxf(acc[mi][ni][1] + bb.y, 0.f));
                *(uint32_t*)(base + 256) = pkh2(fmaxf(acc[mi][ni][2] + bb.x, 0.f),
                                                fmaxf(acc[mi][ni][3] + bb.y, 0.f));
                acc[mi][ni][0] = acc[mi][ni][1] = acc[mi][ni][2] = acc[mi][ni][3] = 0.f;
            }
        }
    }
    __syncthreads();

    // ============================ Layer 2 ================================
    #pragma unroll 1
    for (int c = 0; c < 2; ++c) {
        if (c == 1) ISSUE_W(w3i, b0);   // prefetch W3 into chunk0's buffer
        const char* wb = smem + SM_WB + ((c == 0) ? b0 : (b0 ^ 1)) * WB_BUF;

        uint2 a[2][4][2];
        #pragma unroll
        for (int mi = 0; mi < 4; ++mi) {
            const char* ap = smem + SM_HA + ((wm * 4 + mi) * 8 + c * 4) * 512 + aoff;
            a[0][mi][0] = *(const uint2*)ap;
            a[0][mi][1] = *(const uint2*)(ap + 256);
        }
        #pragma unroll
        for (int k16 = 0; k16 < 4; ++k16) {
            const int cb = k16 & 1, nb = cb ^ 1;
            uint2 b[8];
            #pragma unroll
            for (int ni = 0; ni < 8; ++ni)
                b[ni] = *(const uint2*)(wb + ((wn * 8 + ni) * 4 + k16) * 256 + aoff);
            if (k16 < 3) {
                #pragma unroll
                for (int mi = 0; mi < 4; ++mi) {
                    const char* ap = smem + SM_HA +
                        ((wm * 4 + mi) * 8 + c * 4 + k16 + 1) * 512 + aoff;
                    a[nb][mi][0] = *(const uint2*)ap;
                    a[nb][mi][1] = *(const uint2*)(ap + 256);
                }
            }
            #pragma unroll
            for (int ni = 0; ni < 8; ++ni)
                #pragma unroll
                for (int mi = 0; mi < 4; ++mi)
                    domma(acc[mi][ni], a[cb][mi][0], a[cb][mi][1], b[ni]);
        }
        CP_WAIT0();
        __syncthreads();
    }

    // epilogue 2: bias + relu -> HA (in place; layer-2 reads done at barrier)
    {
        const float* bp = p.b2[gi] + ki * 128;
        #pragma unroll
        for (int ni = 0; ni < 8; ++ni) {
            int col0 = wn * 64 + ni * 8 + 2 * t4;
            float2 bb = *(const float2*)(bp + col0);
            int kt = wn * 4 + (ni >> 1);
            int off = awl + ((ni & 1) << 2);
            #pragma unroll
            for (int mi = 0; mi < 4; ++mi) {
                char* base = smem + SM_HA + ((wm * 4 + mi) * 8 + kt) * 512 + g * 32 + off;
                *(uint32_t*)base = pkh2(fmaxf(acc[mi][ni][0] + bb.x, 0.f),
                                        fmaxf(acc[mi][ni][1] + bb.y, 0.f));
                *(uint32_t*)(base + 256) = pkh2(fmaxf(acc[mi][ni][2] + bb.x, 0.f),
                                                fmaxf(acc[mi][ni][3] + bb.y, 0.f));
                acc[mi][ni][0] = acc[mi][ni][1] = acc[mi][ni][2] = acc[mi][ni][3] = 0.f;
            }
        }
    }
    __syncthreads();

    // ============================ Layer 3 ================================
    {
        const char* wb = smem + SM_WB + b0 * WB_BUF;   // W3 (waited at L2 end)
        uint2 a[2][4][2];
        #pragma unroll
        for (int mi = 0; mi < 4; ++mi) {
            const char* ap = smem + SM_HA + ((wm * 4 + mi) * 8 + 0) * 512 + aoff;
            a[0][mi][0] = *(const uint2*)ap;
            a[0][mi][1] = *(const uint2*)(ap + 256);
        }
        #pragma unroll
        for (int k16 = 0; k16 < 8; ++k16) {
            const int cb = k16 & 1, nb = cb ^ 1;
            uint2 b[4];
            #pragma unroll
            for (int ni = 0; ni < 4; ++ni)
                b[ni] = *(const uint2*)(wb + ((wn * 4 + ni) * 8 + k16) * 256 + aoff);
            if (k16 < 7) {
                #pragma unroll
                for (int mi = 0; mi < 4; ++mi) {
                    const char* ap = smem + SM_HA +
                        ((wm * 4 + mi) * 8 + k16 + 1) * 512 + aoff;
                    a[nb][mi][0] = *(const uint2*)ap;
                    a[nb][mi][1] = *(const uint2*)(ap + 256);
                }
            }
            #pragma unroll
            for (int ni = 0; ni < 4; ++ni)
                #pragma unroll
                for (int mi = 0; mi < 4; ++mi)
                    domma(acc[mi][ni], a[cb][mi][0], a[cb][mi][1], b[ni]);
        }
    }

    // epilogue 3: bias, f32 STG.64 direct
    {
        const float* bp = p.b3[gi] + ki * 64;
        const int oj = c_out[node] * 64;
        #pragma unroll
        for (int ni = 0; ni < 4; ++ni) {
            int col0 = wn * 32 + ni * 8 + 2 * t4;
            float2 bb = *(const float2*)(bp + col0);
            #pragma unroll
            for (int mi = 0; mi < 4; ++mi) {
                size_t ro = (size_t)(m0 + wm * 64 + mi * 16 + g) * 1344 + oj + col0;
                *(float2*)(p.out + ro) =
                    make_float2(acc[mi][ni][0] + bb.x, acc[mi][ni][1] + bb.y);
                *(float2*)(p.out + ro + (size_t)8 * 1344) =
                    make_float2(acc[mi][ni][2] + bb.x, acc[mi][ni][3] + bb.y);
            }
        }
    }
    #undef ISSUE_W
    #undef STORE_X
}

// ------------------------------ launch -------------------------------------

extern "C" void kernel_launch(void* const* d_in, const int* in_sizes, int n_in,
                              void* d_out, int out_size) {
    (void)n_in; (void)out_size;
    Params p;
    p.x = (const float*)d_in[0];
    int idx = 1;
    for (int gi = 0; gi < 5; ++gi) {
        p.w1[gi] = (const float*)d_in[idx++];
        p.b1[gi] = (const float*)d_in[idx++];
        p.w2[gi] = (const float*)d_in[idx++];
        p.b2[gi] = (const float*)d_in[idx++];
        p.w3[gi] = (const float*)d_in[idx++];
        p.b3[gi] = (const float*)d_in[idx++];
    }
    p.out = (float*)d_out;

    const int B = in_sizes[0] / (21 * 64);

    // ONE ballast-free prep launch: 1081344 elements / 256 = 4224 blocks.
    prep_all<<<4224, 256>>>(p);

    cudaFuncSetAttribute(mp17_kernel, cudaFuncAttributeMaxDynamicSharedMemorySize,
                         SMEM_TOTAL);
    dim3 grid(21, B / 128);
    mp17_kernel<<<grid, 128, SMEM_TOTAL>>>(p);
}